// round 13
// baseline (speedup 1.0000x reference)
#include <cuda_runtime.h>
#include <cuda_fp16.h>
#include <cstdint>

#define DI __device__ __forceinline__

// problem dims
#define CC   2048
#define WWD  96
#define HWP  4608          // 48*96
#define NCOL 384           // 4*96 GEMM columns
#define NSTEP 94

// GEMM tiling: CTA 64x96, K split in halves across warp groups; BK=64 per chunk
#define BM 64
#define BN 96
#define BK 64
#define NCH 16             // chunks per K-half (16*64 = 1024)
#define AST 72             // padded fp16 row stride (64+8)
#define A_Hh (BM*AST)      // 4608 halfs (A part of a stage)
#define STG_H (A_Hh + BN*AST)   // 11520 halfs
#define STG_B (STG_H*2)    // 23040 bytes per stage
#define NSLOT 4            // slots per K-half ring
#define RED_OFF (8*STG_B)          // 184320: fp32 reduction region (4*32*49*4 = 25088)
#define TR_OFF  (RED_OFF + 25088)  // 209408: transpose region (96*72*2 = 13824)
#define SMEM_BYTES (TR_OFF + 13824) // 223232
#define TPAD 72
#define NCTA 128

// device scratch (static; allocation-rule safe)
__device__ __half g_w[(size_t)CC * CC];            // 8.4 MB, L2-resident
__device__ __half g_carry[2][(size_t)NCOL * CC];   // 2 x 1.5 MB ping-pong
__device__ unsigned g_bar;                          // grid barrier counter

// ---------------- PTX helpers (base sm_103 ISA only) ----------------
DI uint32_t smem_u32(const void* p) {
    uint32_t a;
    asm("{ .reg .u64 t; cvta.to.shared.u64 t, %1; cvt.u32.u64 %0, t; }" : "=r"(a) : "l"(p));
    return a;
}
DI void cp16(uint32_t s, const void* g) {
    asm volatile("cp.async.cg.shared.global [%0], [%1], 16;" :: "r"(s), "l"(g) : "memory");
}
DI void cp_commit() { asm volatile("cp.async.commit_group;" ::: "memory"); }
DI void cp_wait2()  { asm volatile("cp.async.wait_group 2;" ::: "memory"); }

DI void ldsm4(uint32_t a, uint32_t* r) {
    asm volatile("ldmatrix.sync.aligned.m8n8.x4.shared.b16 {%0,%1,%2,%3},[%4];"
        : "=r"(r[0]), "=r"(r[1]), "=r"(r[2]), "=r"(r[3]) : "r"(a));
}
DI void mma16816(float* d, const uint32_t* a, uint32_t b0, uint32_t b1) {
    asm volatile(
        "mma.sync.aligned.m16n8k16.row.col.f32.f16.f16.f32 "
        "{%0,%1,%2,%3},{%4,%5,%6,%7},{%8,%9},{%0,%1,%2,%3};"
        : "+f"(d[0]), "+f"(d[1]), "+f"(d[2]), "+f"(d[3])
        : "r"(a[0]), "r"(a[1]), "r"(a[2]), "r"(a[3]), "r"(b0), "r"(b1));
}

// ---------------- persistent all-steps kernel ----------------
__global__ void __launch_bounds__(256, 1)
steps_kernel(const float* __restrict__ bias,
             const float* __restrict__ fea, float* __restrict__ out)
{
    extern __shared__ char smc[];
    __half* smh = (__half*)smc;
    float*  smf = (float*)(smc + RED_OFF);
    __half* smt = (__half*)(smc + TR_OFF);
    uint32_t smb = smem_u32(smc);

    const int tid = threadIdx.x, lane = tid & 31, warp = tid >> 5;
    const int mtile = blockIdx.x, ntile = blockIdx.y;
    const int par = warp >> 2;                 // K-half: warps 0-3 -> K[0,1024), 4-7 -> K[1024,2048)
    const int w2 = warp & 3, wm = w2 >> 1, wn = w2 & 1;   // 2x2 warp grid, tile 32x48
    const __half* gA = g_w + (size_t)(mtile * BM) * CC;

    const int lr = lane & 15, lh = (lane >> 4) * 8;
    const int g = lane >> 2, cp2 = (lane & 3) * 2;

    auto ring = [&](int p, int s) -> uint32_t { return smb + (uint32_t)((p * NSLOT + s) * STG_B); };
    const uint32_t aoff0 = (uint32_t)((wm * 32 + lr) * AST + lh) * 2;          // + mi*16*AST*2
    const uint32_t boff0 = (uint32_t)(A_Hh + (wn * 48 + lr) * AST + lh) * 2;   // + nb*16*AST*2

    // A unit loader: u in [0,512)
    auto loadA = [&](int p, int c, int u) {
        int r = u >> 3, ku = u & 7;
        cp16(ring(p, c & (NSLOT - 1)) + (uint32_t)(r * AST + ku * 8) * 2,
             gA + (size_t)r * CC + p * 1024 + c * BK + ku * 8);
    };

    float bv[2][2];
    #pragma unroll
    for (int mi = 0; mi < 2; mi++)
        #pragma unroll
        for (int hi = 0; hi < 2; hi++)
            bv[mi][hi] = bias[mtile * BM + wm * 32 + mi * 16 + g + hi * 8];

    #pragma unroll 1
    for (int step = 0; step < NSTEP; step++) {
        const int pin = step & 1;
        const __half* __restrict__ cin  = g_carry[pin];
        __half* __restrict__ cout = g_carry[pin ^ 1];
        const int h = (step < 47) ? (step + 1) : (93 - step);
        const float* __restrict__ src = (step < 47) ? fea : out;
        const __half* gB = cin + (size_t)(ntile * BN) * CC;

        auto loadB = [&](int p, int c, int u) {   // u in [0,768)
            int r = u >> 3, ku = u & 7;
            cp16(ring(p, c & (NSLOT - 1)) + (uint32_t)(A_Hh + r * AST + ku * 8) * 2,
                 gB + (size_t)r * CC + p * 1024 + c * BK + ku * 8);
        };
        auto load_unit = [&](int c, int u) {      // u in [0,2560): both halves' chunk c
            int p = (u >= 1280);
            int uu = u - p * 1280;
            if (uu < 512) loadA(p, c, uu);
            else          loadB(p, c, uu - 512);
        };

        // ---- pre-barrier: prefetch A of chunks 0,1 for both halves (W is step-invariant) ----
        #pragma unroll
        for (int c = 0; c < 2; c++)
            #pragma unroll
            for (int p = 0; p < 2; p++)
                #pragma unroll
                for (int j = 0; j < 2; j++) loadA(p, c, tid + j * 256);

        // ---- grid barrier ----
        if (step > 0) {
            if (tid == 0) {
                __threadfence();
                atomicAdd(&g_bar, 1u);
                const unsigned target = (unsigned)(NCTA * step);
                unsigned v;
                do {
                    asm volatile("ld.acquire.gpu.u32 %0, [%1];" : "=r"(v) : "l"(&g_bar));
                    if (v < target) __nanosleep(64);
                } while (v < target);
            }
            __syncthreads();
        }

        // ---- B of chunks 0,1 + full chunk 2 ----
        #pragma unroll
        for (int p = 0; p < 2; p++)
            #pragma unroll
            for (int j = 0; j < 3; j++) loadB(p, 0, tid + j * 256);
        cp_commit();                                    // G0 = {A0,A1,B0}
        #pragma unroll
        for (int p = 0; p < 2; p++)
            #pragma unroll
            for (int j = 0; j < 3; j++) loadB(p, 1, tid + j * 256);
        cp_commit();                                    // G1 = {B1}
        #pragma unroll
        for (int j = 0; j < 10; j++) load_unit(2, tid + j * 256);
        cp_commit();                                    // G2 = chunk2

        float acc[2][6][4];
        #pragma unroll
        for (int mi = 0; mi < 2; mi++)
            #pragma unroll
            for (int ni = 0; ni < 6; ni++)
                #pragma unroll
                for (int e = 0; e < 4; e++) acc[mi][ni][e] = 0.f;

        #pragma unroll 1
        for (int t = 0; t < NCH; t++) {
            cp_wait2();
            __syncthreads();
            uint32_t slot = ring(par, t & (NSLOT - 1));

            uint32_t a[2][2][4], b[2][3][4];
            #pragma unroll
            for (int mi = 0; mi < 2; mi++)
                ldsm4(slot + aoff0 + (uint32_t)(mi * 16 * AST) * 2, a[0][mi]);
            #pragma unroll
            for (int nb = 0; nb < 3; nb++)
                ldsm4(slot + boff0 + (uint32_t)(nb * 16 * AST) * 2, b[0][nb]);

            const int pf = (t + 3 < NCH);
            #pragma unroll
            for (int kk = 0; kk < 4; kk++) {
                int cur = kk & 1, nxt = cur ^ 1;
                if (kk < 3) {
                    uint32_t ko = (uint32_t)((kk + 1) * 16) * 2;
                    #pragma unroll
                    for (int mi = 0; mi < 2; mi++)
                        ldsm4(slot + aoff0 + (uint32_t)(mi * 16 * AST) * 2 + ko, a[nxt][mi]);
                    #pragma unroll
                    for (int nb = 0; nb < 3; nb++)
                        ldsm4(slot + boff0 + (uint32_t)(nb * 16 * AST) * 2 + ko, b[nxt][nb]);
                    // spread next-chunk loads: 4,3,3 units at kk=0,1,2
                    if (pf) {
                        int j0 = (kk == 0) ? 0 : (kk == 1 ? 4 : 7);
                        int jn = (kk == 0) ? 4 : (kk == 1 ? 7 : 10);
                        for (int j = j0; j < jn; j++) load_unit(t + 3, tid + j * 256);
                    }
                }
                #pragma unroll
                for (int mi = 0; mi < 2; mi++)
                    #pragma unroll
                    for (int nb = 0; nb < 3; nb++) {
                        mma16816(acc[mi][2 * nb],     a[cur][mi], b[cur][nb][0], b[cur][nb][2]);
                        mma16816(acc[mi][2 * nb + 1], a[cur][mi], b[cur][nb][1], b[cur][nb][3]);
                    }
            }
            cp_commit();
        }

        // ---- epilogue: reduce K-halves via smem, then relu+bias+residual + carry ----
        __syncthreads();
        if (par == 1) {
            #pragma unroll
            for (int mi = 0; mi < 2; mi++)
                #pragma unroll
                for (int ni = 0; ni < 6; ni++)
                    #pragma unroll
                    for (int e = 0; e < 4; e++)
                        smf[(w2 * 32 + lane) * 49 + mi * 24 + ni * 4 + e] = acc[mi][ni][e];
        }
        __syncthreads();
        if (par == 0) {
            #pragma unroll
            for (int mi = 0; mi < 2; mi++)
                #pragma unroll
                for (int ni = 0; ni < 6; ni++)
                    #pragma unroll
                    for (int e = 0; e < 4; e++) {
                        float v = acc[mi][ni][e] + smf[(w2 * 32 + lane) * 49 + mi * 24 + ni * 4 + e];
                        int o_l = wm * 32 + mi * 16 + g + (e >> 1) * 8;   // 0..63
                        int j_l = wn * 48 + ni * 8 + cp2 + (e & 1);       // 0..95 (== w)
                        int o = mtile * BM + o_l;
                        size_t idx = (size_t)(ntile * CC + o) * HWP + (size_t)h * WWD + j_l;
                        v += bv[mi][e >> 1];
                        v = fmaxf(v, 0.f) + src[idx];
                        out[idx] = v;
                        smt[j_l * TPAD + o_l] = __float2half(v);
                    }
        }
        __syncthreads();
        // coalesced carry writes: 96 rows x 8 segs = 768 16B segments, 3 per thread
        #pragma unroll
        for (int t2 = 0; t2 < 3; t2++) {
            int seg = tid + t2 * 256;
            int j_l = seg >> 3, os = (seg & 7) * 8;
            uint4 val = *reinterpret_cast<const uint4*>(&smt[j_l * TPAD + os]);
            *reinterpret_cast<uint4*>(&cout[(size_t)(ntile * BN + j_l) * CC + mtile * BM + os]) = val;
        }
        __syncthreads();
    }
}

// ---------------- prep kernels ----------------
__global__ void wprep(const float* __restrict__ W) {
    int i = blockIdx.x * 256 + threadIdx.x;
    if (i >= CC * CC) return;
    g_w[i] = __float2half(W[(size_t)i * 9 + 4]);   // center tap of KH=9
}

__global__ void initk(const float* __restrict__ fea, float* __restrict__ out) {
    int i = blockIdx.x * 256 + threadIdx.x;
    if (i >= NCOL * CC) return;
    int o = i & (CC - 1), j = i >> 11;
    int n = j / WWD, w = j - n * WWD;
    size_t gidx = (size_t)(n * CC + o) * HWP + w;   // h = 0
    float v = fea[gidx];
    out[gidx] = v;                                   // down[0] = x[0]
    g_carry[0][(size_t)j * CC + o] = __float2half(v);
}

// ---------------- launch ----------------
extern "C" void kernel_launch(void* const* d_in, const int* in_sizes, int n_in,
                              void* d_out, int out_size)
{
    const float* fea = (const float*)d_in[0];
    const float* W   = (const float*)d_in[1];
    const float* b   = (const float*)d_in[2];
    float* out = (float*)d_out;

    cudaFuncSetAttribute(steps_kernel, cudaFuncAttributeMaxDynamicSharedMemorySize, SMEM_BYTES);

    void* bar_addr = nullptr;
    cudaGetSymbolAddress(&bar_addr, g_bar);
    cudaMemsetAsync(bar_addr, 0, sizeof(unsigned));   // reset barrier each launch/replay

    wprep<<<(CC * CC + 255) / 256, 256>>>(W);
    initk<<<(NCOL * CC + 255) / 256, 256>>>(fea, out);

    steps_kernel<<<dim3(32, 4), 256, SMEM_BYTES>>>(b, fea, out);
}